// round 6
// baseline (speedup 1.0000x reference)
#include <cuda_runtime.h>
#include <cstdint>

#define NN 2048
#define UU 64
#define RR 64

// ---- scratch (device globals; allocation is forbidden) ----
__device__ float g_S[(size_t)NN * NN];     // 16 MB score matrix
__device__ float g_head[NN];
__device__ float g_tail[NN];
__device__ float g_colinv[NN];             // 1 / sum_i exp(S[i,j])
__device__ float g_proped[NN * UU];        // weight_masked @ feature

// ---------------------------------------------------------------------------
// Kernel A: head[n] = relu(feature[n]·head_w + head_b), tail likewise
// ---------------------------------------------------------------------------
__global__ __launch_bounds__(256)
void head_tail_kernel(const float* __restrict__ feature,
                      const float* __restrict__ head_w,
                      const float* __restrict__ head_b,
                      const float* __restrict__ tail_w,
                      const float* __restrict__ tail_b) {
    int n = blockIdx.x * blockDim.x + threadIdx.x;
    if (n >= NN) return;
    const float4* f  = (const float4*)(feature + (size_t)n * UU);
    const float4* hw = (const float4*)head_w;
    const float4* tw = (const float4*)tail_w;
    float h = 0.f, t = 0.f;
#pragma unroll
    for (int k = 0; k < UU / 4; k++) {
        float4 v = f[k], a = hw[k], b = tw[k];
        h += v.x * a.x + v.y * a.y + v.z * a.z + v.w * a.w;
        t += v.x * b.x + v.y * b.y + v.z * b.z + v.w * b.w;
    }
    g_head[n] = fmaxf(h + head_b[0], 0.f);
    g_tail[n] = fmaxf(t + tail_b[0], 0.f);
}

// ---------------------------------------------------------------------------
// Kernel B (dominant, DRAM-bound): per pair p=(i,j)
//   S[p] = rel_mask[p] + head[i] + tail[j] + relu(relation[p,:]·rel_w + rel_b)
// 16 lanes per pair, each lane one float4 (perfectly coalesced 256B/pair).
// 64 pairs per 256-thread block (4 pairs per 16-lane group for MLP).
// ---------------------------------------------------------------------------
__global__ __launch_bounds__(256)
void score_kernel(const float* __restrict__ relation,
                  const float* __restrict__ rel_mask,
                  const float* __restrict__ rel_w,
                  const float* __restrict__ rel_b,
                  float* __restrict__ S) {
    __shared__ float4 w4[16];
    int tid = threadIdx.x;
    if (tid < 16) w4[tid] = ((const float4*)rel_w)[tid];
    __syncthreads();

    int lane = tid & 15;
    int g    = tid >> 4;                 // 16 groups of 16 lanes
    size_t pb = (size_t)blockIdx.x * 64;
    float4 w = w4[lane];
    float rb = rel_b[0];

    const float4* rel4 = (const float4*)relation;

    // batch the 4 loads for MLP
    float4 r0 = rel4[(pb + 0 * 16 + g) * 16 + lane];
    float4 r1 = rel4[(pb + 1 * 16 + g) * 16 + lane];
    float4 r2 = rel4[(pb + 2 * 16 + g) * 16 + lane];
    float4 r3 = rel4[(pb + 3 * 16 + g) * 16 + lane];

#pragma unroll
    for (int k = 0; k < 4; k++) {
        float4 r = (k == 0) ? r0 : (k == 1) ? r1 : (k == 2) ? r2 : r3;
        float d = r.x * w.x + r.y * w.y + r.z * w.z + r.w * w.w;
#pragma unroll
        for (int o = 8; o; o >>= 1)
            d += __shfl_down_sync(0xffffffffu, d, o, 16);
        if (lane == 0) {
            size_t p = pb + (size_t)k * 16 + g;
            int i = (int)(p >> 11);
            int j = (int)(p & (NN - 1));
            S[p] = rel_mask[p] + g_head[i] + g_tail[j] + fmaxf(d + rb, 0.f);
        }
    }
}

// ---------------------------------------------------------------------------
// Kernel C: colinv[j] = 1 / sum_i exp(S[i,j])   (values small enough: no max)
// 32 cols x 8 row-threads per block; deterministic in-block reduction.
// ---------------------------------------------------------------------------
__global__ __launch_bounds__(256)
void colsum_kernel() {
    __shared__ float part[8][32];
    int c = threadIdx.x & 31;
    int r = threadIdx.x >> 5;
    int col = blockIdx.x * 32 + c;
    float s = 0.f;
    for (int row = r; row < NN; row += 8)
        s += __expf(g_S[(size_t)row * NN + col]);
    part[r][c] = s;
    __syncthreads();
    if (r == 0) {
        float t = 0.f;
#pragma unroll
        for (int k = 0; k < 8; k++) t += part[k][c];
        g_colinv[col] = 1.0f / t;
    }
}

// ---------------------------------------------------------------------------
// Kernel D: proped[i,u] = sum_j exp(S[i,j]) * colinv[j] * feature[j,u]
// 16 rows x 64 cols per block; j-chunks of 128 staged through smem.
// ---------------------------------------------------------------------------
__global__ __launch_bounds__(256)
void agg_kernel(const float* __restrict__ feature) {
    __shared__ float feat_s[128][UU];   // 32 KB
    __shared__ float ps[16][128];       //  8 KB
    int tid = threadIdx.x;              // 256
    int u  = tid & 63;
    int ig = tid >> 6;                  // 0..3, each handles 4 rows
    int i0 = blockIdx.x * 16;

    float acc0 = 0.f, acc1 = 0.f, acc2 = 0.f, acc3 = 0.f;

    for (int j0 = 0; j0 < NN; j0 += 128) {
        __syncthreads();
        // load feature chunk [128][64] (8192 floats = 2048 float4)
        const float4* f4 = (const float4*)(feature + (size_t)j0 * UU);
        float4* fs4 = (float4*)&feat_s[0][0];
#pragma unroll
        for (int k = 0; k < 8; k++) fs4[k * 256 + tid] = f4[k * 256 + tid];
        // compute softmax-prob tile [16][128]
#pragma unroll
        for (int k = 0; k < 8; k++) {
            int l = k * 256 + tid;
            int ii = l >> 7, jj = l & 127;
            ps[ii][jj] = __expf(g_S[(size_t)(i0 + ii) * NN + j0 + jj]) *
                         g_colinv[j0 + jj];
        }
        __syncthreads();
#pragma unroll 4
        for (int jj = 0; jj < 128; jj++) {
            float f = feat_s[jj][u];
            acc0 += ps[ig * 4 + 0][jj] * f;
            acc1 += ps[ig * 4 + 1][jj] * f;
            acc2 += ps[ig * 4 + 2][jj] * f;
            acc3 += ps[ig * 4 + 3][jj] * f;
        }
    }
    g_proped[(size_t)(i0 + ig * 4 + 0) * UU + u] = acc0;
    g_proped[(size_t)(i0 + ig * 4 + 1) * UU + u] = acc1;
    g_proped[(size_t)(i0 + ig * 4 + 2) * UU + u] = acc2;
    g_proped[(size_t)(i0 + ig * 4 + 3) * UU + u] = acc3;
}

// ---------------------------------------------------------------------------
// Kernel E: prediction + losses, single block (256 thr x 8 rows),
// deterministic reduction.
// rank_loss = mean(relu(rr_i*rr_j*m_i*m_j)) = (P^2 + Ng^2)/N^2
//   with a_i = rr_i*m_i, P = sum(a_i>0), Ng = sum(a_i<0).
// ---------------------------------------------------------------------------
__global__ __launch_bounds__(256)
void loss_kernel(const float* __restrict__ feature,
                 const float* __restrict__ pred_w,
                 const float* __restrict__ pred_b,
                 const float* __restrict__ base_price,
                 const float* __restrict__ ground_truth,
                 const float* __restrict__ mask,
                 float* __restrict__ out, int out_size) {
    __shared__ float pw[2 * UU];
    __shared__ float s_sq[8], s_pos[8], s_neg[8];
    int tid = threadIdx.x;                // 256
    if (tid < 2 * UU) pw[tid] = pred_w[tid];
    __syncthreads();

    float pb = pred_b[0];
    float sq = 0.f, pos = 0.f, neg = 0.f;
    for (int k = 0; k < 8; k++) {
        int row = tid + k * 256;
        const float4* f = (const float4*)(feature + (size_t)row * UU);
        const float4* p = (const float4*)(g_proped + (size_t)row * UU);
        const float4* w0 = (const float4*)pw;
        const float4* w1 = (const float4*)(pw + UU);
        float d = 0.f;
#pragma unroll
        for (int r = 0; r < UU / 4; r++) {
            float4 v = f[r], w = w0[r];
            d += v.x * w.x + v.y * w.y + v.z * w.z + v.w * w.w;
        }
#pragma unroll
        for (int r = 0; r < UU / 4; r++) {
            float4 v = p[r], w = w1[r];
            d += v.x * w.x + v.y * w.y + v.z * w.z + v.w * w.w;
        }
        d += pb;
        float pred = (d >= 0.f) ? d : 0.2f * d;       // leaky_relu
        float bpv  = base_price[row];
        float rr   = (pred - bpv) / bpv;
        float diff = rr - ground_truth[row];
        sq += diff * diff;
        float a = rr * mask[row];
        pos += (a > 0.f) ? a : 0.f;
        neg += (a < 0.f) ? a : 0.f;
    }
#pragma unroll
    for (int o = 16; o; o >>= 1) {
        sq  += __shfl_down_sync(0xffffffffu, sq,  o);
        pos += __shfl_down_sync(0xffffffffu, pos, o);
        neg += __shfl_down_sync(0xffffffffu, neg, o);
    }
    if ((tid & 31) == 0) {
        s_sq[tid >> 5] = sq; s_pos[tid >> 5] = pos; s_neg[tid >> 5] = neg;
    }
    __syncthreads();
    if (tid == 0) {
        float tsq = 0.f, tp = 0.f, tn = 0.f;
#pragma unroll
        for (int k = 0; k < 8; k++) { tsq += s_sq[k]; tp += s_pos[k]; tn += s_neg[k]; }
        float reg  = tsq;
        float rank = (tp * tp + tn * tn) / ((float)NN * (float)NN);
        float loss = reg + 1.0f * rank;   // ALPHA = 1.0
        out[0] = loss;
        if (out_size > 1) out[1] = reg;
        if (out_size > 2) out[2] = rank;
    }
}

extern "C" void kernel_launch(void* const* d_in, const int* in_sizes, int n_in,
                              void* d_out, int out_size) {
    const float* feature      = (const float*)d_in[0];
    const float* relation     = (const float*)d_in[1];
    const float* rel_mask     = (const float*)d_in[2];
    const float* base_price   = (const float*)d_in[3];
    const float* ground_truth = (const float*)d_in[4];
    const float* mask         = (const float*)d_in[5];
    const float* rel_w        = (const float*)d_in[6];
    const float* rel_b        = (const float*)d_in[7];
    const float* head_w       = (const float*)d_in[8];
    const float* head_b       = (const float*)d_in[9];
    const float* tail_w       = (const float*)d_in[10];
    const float* tail_b       = (const float*)d_in[11];
    const float* pred_w       = (const float*)d_in[12];
    const float* pred_b       = (const float*)d_in[13];
    float* out = (float*)d_out;

    float* S;
    cudaGetSymbolAddress((void**)&S, g_S);

    head_tail_kernel<<<(NN + 255) / 256, 256>>>(feature, head_w, head_b, tail_w, tail_b);
    score_kernel<<<(size_t)NN * NN / 64, 256>>>(relation, rel_mask, rel_w, rel_b, S);
    colsum_kernel<<<NN / 32, 256>>>();
    agg_kernel<<<NN / 16, 256>>>(feature);
    loss_kernel<<<1, 256>>>(feature, pred_w, pred_b, base_price, ground_truth,
                            mask, out, out_size);
}